// round 1
// baseline (speedup 1.0000x reference)
#include <cuda_runtime.h>

#define BATCH 4096
#define INF   1024
#define OUTF  1024
#define NL    16

#define BM 128
#define BN 128
#define BSPAD 132   // Bs row pad (multiple of 4 for float4 alignment)

// Gating output scratch (device global: allocation-free per harness rules)
__device__ float g_gate[BATCH * NL];

// ---------------------------------------------------------------------------
// Kernel 1: gating — g = softmax(x @ gw + gb), one block per batch row.
// ---------------------------------------------------------------------------
__global__ __launch_bounds__(256)
void gating_kernel(const float* __restrict__ x,
                   const float* __restrict__ gw,
                   const float* __restrict__ gb) {
    int b   = blockIdx.x;
    int tid = threadIdx.x;          // 256 threads
    int l   = tid & 15;             // leaf
    int i0  = tid >> 4;             // 0..15 partial-sum slot

    const float* xr = x + b * INF;
    float acc = 0.f;
    #pragma unroll 4
    for (int i = i0; i < INF; i += 16)
        acc = fmaf(xr[i], gw[i * NL + l], acc);

    __shared__ float red[16][17];
    __shared__ float lg[16];
    __shared__ float ex[16];
    red[i0][l] = acc;
    __syncthreads();

    if (tid < 16) {
        float s = gb[tid];
        #pragma unroll
        for (int j = 0; j < 16; j++) s += red[j][tid];
        lg[tid] = s;
    }
    __syncthreads();
    if (tid < 16) {
        float m = lg[0];
        #pragma unroll
        for (int j = 1; j < 16; j++) m = fmaxf(m, lg[j]);
        ex[tid] = __expf(lg[tid] - m);
    }
    __syncthreads();
    if (tid < 16) {
        float s = 0.f;
        #pragma unroll
        for (int j = 0; j < 16; j++) s += ex[j];
        g_gate[b * NL + tid] = ex[tid] / s;
    }
}

// ---------------------------------------------------------------------------
// Kernel 2: fused GEMM.
//   out[b,o] = sum_{i,l} (x[b,i]*g[b,l]) * pw[o,i,l]  +  sum_l g[b,l]*pb[o,l]
// Viewed as C = Y @ PW^T with K = i*16+l (16384). K-tile = 16 = one i value
// (pw's innermost l is contiguous). Y tile synthesized in smem from x and the
// per-block g tile. 128x128 C tile, 256 threads, 8x8 microtile/thread,
// double-buffered smem.
// ---------------------------------------------------------------------------
__global__ __launch_bounds__(256, 2)
void moe_gemm_kernel(const float* __restrict__ x,
                     const float* __restrict__ pw,
                     const float* __restrict__ pb,
                     float* __restrict__ out) {
    __shared__ float As[2][NL][BM];       // Y tile:  As[l][m] = x[b,i]*g[b,l]
    __shared__ float Bs[2][NL][BSPAD];    // PW tile: Bs[l][o] = pw[o,i,l]
    __shared__ float gs[BM][17];          // gating tile for this m-block

    const int tid   = threadIdx.x;
    const int m_blk = blockIdx.y * BM;
    const int n_blk = blockIdx.x * BN;

    // --- load g tile (128 x 16), 8 values per thread ---
    {
        int m  = tid >> 1;
        int l0 = (tid & 1) * 8;
        #pragma unroll
        for (int j = 0; j < 8; j++)
            gs[m][l0 + j] = g_gate[(m_blk + m) * NL + l0 + j];
    }

    // --- loader index sets ---
    const int oL  = tid >> 2;            // 0..63  (o within tile; +64 second half)
    const int l4  = (tid & 3) * 4;       // l base for float4 load
    const int am  = tid & 127;           // m for A-generation
    const int al0 = (tid >> 7) * 8;      // l base (0 or 8) for A-generation

    // --- compute index sets ---
    const int tx = tid & 15, ty = tid >> 4;
    const int n0 = tx * 8, m0 = ty * 8;

    const float* pwB = pw + (size_t)n_blk * INF * NL;

    // ---- prefetch K-tile 0 into registers ----
    float4 rb0 = *(const float4*)(pwB + (size_t)oL        * INF * NL + l4);
    float4 rb1 = *(const float4*)(pwB + (size_t)(oL + 64) * INF * NL + l4);
    float  rx  = x[(m_blk + am) * INF + 0];

    __syncthreads();   // gs visible

    // store tile 0
    Bs[0][l4 + 0][oL] = rb0.x;  Bs[0][l4 + 1][oL] = rb0.y;
    Bs[0][l4 + 2][oL] = rb0.z;  Bs[0][l4 + 3][oL] = rb0.w;
    Bs[0][l4 + 0][oL + 64] = rb1.x;  Bs[0][l4 + 1][oL + 64] = rb1.y;
    Bs[0][l4 + 2][oL + 64] = rb1.z;  Bs[0][l4 + 3][oL + 64] = rb1.w;
    #pragma unroll
    for (int j = 0; j < 8; j++)
        As[0][al0 + j][am] = rx * gs[am][al0 + j];
    __syncthreads();

    float acc[8][8];
    #pragma unroll
    for (int mi = 0; mi < 8; mi++)
        #pragma unroll
        for (int ni = 0; ni < 8; ni++) acc[mi][ni] = 0.f;

    // ---- main K loop: i = 0..1023, each iteration one K-tile of 16 leaves ----
    #pragma unroll 1
    for (int i = 0; i < INF; i++) {
        const int cur = i & 1, nxt = cur ^ 1;

        if (i + 1 < INF) {
            const int ip = i + 1;
            rb0 = *(const float4*)(pwB + (size_t)oL        * INF * NL + ip * NL + l4);
            rb1 = *(const float4*)(pwB + (size_t)(oL + 64) * INF * NL + ip * NL + l4);
            rx  = x[(m_blk + am) * INF + ip];
        }

        #pragma unroll
        for (int l = 0; l < NL; l++) {
            float a[8], b[8];
            *(float4*)&a[0] = *(const float4*)&As[cur][l][m0];
            *(float4*)&a[4] = *(const float4*)&As[cur][l][m0 + 4];
            *(float4*)&b[0] = *(const float4*)&Bs[cur][l][n0];
            *(float4*)&b[4] = *(const float4*)&Bs[cur][l][n0 + 4];
            #pragma unroll
            for (int mi = 0; mi < 8; mi++)
                #pragma unroll
                for (int ni = 0; ni < 8; ni++)
                    acc[mi][ni] = fmaf(a[mi], b[ni], acc[mi][ni]);
        }

        if (i + 1 < INF) {
            Bs[nxt][l4 + 0][oL] = rb0.x;  Bs[nxt][l4 + 1][oL] = rb0.y;
            Bs[nxt][l4 + 2][oL] = rb0.z;  Bs[nxt][l4 + 3][oL] = rb0.w;
            Bs[nxt][l4 + 0][oL + 64] = rb1.x;  Bs[nxt][l4 + 1][oL + 64] = rb1.y;
            Bs[nxt][l4 + 2][oL + 64] = rb1.z;  Bs[nxt][l4 + 3][oL + 64] = rb1.w;
            #pragma unroll
            for (int j = 0; j < 8; j++)
                As[nxt][al0 + j][am] = rx * gs[am][al0 + j];
        }
        __syncthreads();
    }

    // ---- bias as one extra K-tile: As = g, Bs = pb ----
    {
        float4 pb0 = *(const float4*)(pb + (n_blk + oL)      * NL + l4);
        float4 pb1 = *(const float4*)(pb + (n_blk + oL + 64) * NL + l4);
        Bs[0][l4 + 0][oL] = pb0.x;  Bs[0][l4 + 1][oL] = pb0.y;
        Bs[0][l4 + 2][oL] = pb0.z;  Bs[0][l4 + 3][oL] = pb0.w;
        Bs[0][l4 + 0][oL + 64] = pb1.x;  Bs[0][l4 + 1][oL + 64] = pb1.y;
        Bs[0][l4 + 2][oL + 64] = pb1.z;  Bs[0][l4 + 3][oL + 64] = pb1.w;
        #pragma unroll
        for (int j = 0; j < 8; j++)
            As[0][al0 + j][am] = gs[am][al0 + j];
        __syncthreads();

        #pragma unroll
        for (int l = 0; l < NL; l++) {
            float a[8], b[8];
            *(float4*)&a[0] = *(const float4*)&As[0][l][m0];
            *(float4*)&a[4] = *(const float4*)&As[0][l][m0 + 4];
            *(float4*)&b[0] = *(const float4*)&Bs[0][l][n0];
            *(float4*)&b[4] = *(const float4*)&Bs[0][l][n0 + 4];
            #pragma unroll
            for (int mi = 0; mi < 8; mi++)
                #pragma unroll
                for (int ni = 0; ni < 8; ni++)
                    acc[mi][ni] = fmaf(a[mi], b[ni], acc[mi][ni]);
        }
    }

    // ---- store C ----
    #pragma unroll
    for (int mi = 0; mi < 8; mi++) {
        float* orow = out + (size_t)(m_blk + m0 + mi) * OUTF + n_blk + n0;
        float4 v0 = make_float4(acc[mi][0], acc[mi][1], acc[mi][2], acc[mi][3]);
        float4 v1 = make_float4(acc[mi][4], acc[mi][5], acc[mi][6], acc[mi][7]);
        *(float4*)(orow)     = v0;
        *(float4*)(orow + 4) = v1;
    }
}

// ---------------------------------------------------------------------------
// Launch: gating, then fused GEMM (stream-ordered; graph-capturable).
// Inputs per metadata order: x, gw, gb, pw, pb. Output: float32 [4096,1024].
// ---------------------------------------------------------------------------
extern "C" void kernel_launch(void* const* d_in, const int* in_sizes, int n_in,
                              void* d_out, int out_size) {
    const float* x  = (const float*)d_in[0];
    const float* gw = (const float*)d_in[1];
    const float* gb = (const float*)d_in[2];
    const float* pw = (const float*)d_in[3];
    const float* pb = (const float*)d_in[4];
    float* out = (float*)d_out;

    gating_kernel<<<BATCH, 256>>>(x, gw, gb);

    dim3 grid(OUTF / BN, BATCH / BM);   // (8, 32)
    moe_gemm_kernel<<<grid, 256>>>(x, pw, pb, out);
}

// round 3
// speedup vs baseline: 5.1813x; 5.1813x over previous
#include <cuda_runtime.h>
#include <cstdint>

#define BATCH 4096
#define INF   1024
#define OUTF  1024
#define NL    16

#define BM 128
#define BN 256
#define BK 32                  // kcat per chunk = 2 i-values x 16 leaves
#define NIT (INF/2)            // 512 pw chunks
#define NTOT (NIT+1)           // +1 bias tile

// smem layout (floats)
#define A_BUF_F   4096         // 8 mtiles x 4 ksteps x 32 lanes x 4
#define B_PITCH   36           // floats per B row (144B = 9x16B, conflict-free)
#define B_BUF_F   (BN*B_PITCH) // 9216
#define A_OFF_F   0
#define B_OFF_F   (3*A_BUF_F)              // 12288
#define GS_OFF_F  (B_OFF_F + 3*B_BUF_F)    // 39936
#define GS_PITCH  20
#define SMEM_F    (GS_OFF_F + BM*GS_PITCH) // 42496 floats
#define SMEM_B_TOTAL (SMEM_F*4)            // 169984 bytes

// device scratch (allocation-free)
__device__ float g_gate[BATCH * NL];
__device__ float g_xT[INF * BATCH];            // x transposed [i][b], 16MB
__device__ float g_pwc[OUTF * INF * NL];       // pw rounded to tf32, 64MB

__device__ __forceinline__ uint32_t smem_u32_of(const void* p) {
    uint32_t a;
    asm("{ .reg .u64 t; cvta.to.shared.u64 t, %1; cvt.u32.u64 %0, t; }" : "=r"(a) : "l"(p));
    return a;
}
__device__ __forceinline__ uint32_t tf32r(float f) {
    uint32_t u;
    asm("cvt.rna.tf32.f32 %0, %1;" : "=r"(u) : "f"(f));
    return u;
}
__device__ __forceinline__ void cp_async16(uint32_t sa, const void* ga) {
    asm volatile("cp.async.cg.shared.global [%0], [%1], 16;" :: "r"(sa), "l"(ga));
}
__device__ __forceinline__ void mma_tf32(float* c, const uint32_t* a, uint32_t b0, uint32_t b1) {
    asm volatile(
        "mma.sync.aligned.m16n8k8.row.col.f32.tf32.tf32.f32 "
        "{%0,%1,%2,%3}, {%4,%5,%6,%7}, {%8,%9}, {%0,%1,%2,%3};"
        : "+f"(c[0]), "+f"(c[1]), "+f"(c[2]), "+f"(c[3])
        : "r"(a[0]), "r"(a[1]), "r"(a[2]), "r"(a[3]), "r"(b0), "r"(b1));
}

// ---------------------------------------------------------------------------
// x transpose: g_xT[i][b] = x[b][i]
// ---------------------------------------------------------------------------
__global__ __launch_bounds__(256)
void transpose_x_kernel(const float* __restrict__ x) {
    __shared__ float t[32][33];
    int i0 = blockIdx.x * 32, b0 = blockIdx.y * 32;
    int tx = threadIdx.x, ty = threadIdx.y;      // 32 x 8
    #pragma unroll
    for (int j = 0; j < 32; j += 8)
        t[ty + j][tx] = x[(size_t)(b0 + ty + j) * INF + i0 + tx];
    __syncthreads();
    #pragma unroll
    for (int j = 0; j < 32; j += 8)
        g_xT[(size_t)(i0 + ty + j) * BATCH + b0 + tx] = t[tx][ty + j];
}

// ---------------------------------------------------------------------------
// pw -> tf32-rounded copy
// ---------------------------------------------------------------------------
__global__ __launch_bounds__(256)
void conv_pw_kernel(const float* __restrict__ pw) {
    size_t idx = (size_t)blockIdx.x * 256 + threadIdx.x;
    float4 v = ((const float4*)pw)[idx];
    float4 o;
    o.x = __uint_as_float(tf32r(v.x));
    o.y = __uint_as_float(tf32r(v.y));
    o.z = __uint_as_float(tf32r(v.z));
    o.w = __uint_as_float(tf32r(v.w));
    ((float4*)g_pwc)[idx] = o;
}

// ---------------------------------------------------------------------------
// gating: g = softmax(x @ gw + gb). Warp per row, gw cached in smem.
// ---------------------------------------------------------------------------
__global__ __launch_bounds__(256)
void gating_kernel(const float* __restrict__ x,
                   const float* __restrict__ gw,
                   const float* __restrict__ gb) {
    extern __shared__ float gw_s[];   // [1024][17]
    int tid = threadIdx.x, warp = tid >> 5, lane = tid & 31;

    for (int idx = tid; idx < INF * NL; idx += 256) {
        int i = idx >> 4, l = idx & 15;
        gw_s[i * 17 + l] = gw[idx];
    }
    __syncthreads();

    int row = blockIdx.x * 8 + warp;
    const float* xr = x + (size_t)row * INF;

    float acc[16];
    #pragma unroll
    for (int l = 0; l < 16; l++) acc[l] = 0.f;

    #pragma unroll 4
    for (int jj = 0; jj < 32; jj++) {
        int i = lane + 32 * jj;
        float xv = xr[i];
        const float* gr = gw_s + i * 17;
        #pragma unroll
        for (int l = 0; l < 16; l++) acc[l] = fmaf(xv, gr[l], acc[l]);
    }
    #pragma unroll
    for (int o = 16; o > 0; o >>= 1)
        #pragma unroll
        for (int l = 0; l < 16; l++)
            acc[l] += __shfl_xor_sync(0xffffffffu, acc[l], o);

    if (lane < 16) {
        float v[16], m = -1e30f;
        #pragma unroll
        for (int l = 0; l < 16; l++) { v[l] = acc[l] + gb[l]; m = fmaxf(m, v[l]); }
        float s = 0.f;
        #pragma unroll
        for (int l = 0; l < 16; l++) { v[l] = __expf(v[l] - m); s += v[l]; }
        g_gate[row * NL + lane] = v[lane] / s;
    }
}

// ---------------------------------------------------------------------------
// main GEMM: out = Y @ PW^T + g @ pb^T via mma.sync tf32 m16n8k8
// ---------------------------------------------------------------------------
__global__ __launch_bounds__(256, 1)
void moe_mma_kernel(const float* __restrict__ pb, float* __restrict__ out) {
    extern __shared__ float sm[];
    const int tid  = threadIdx.x;
    const int warp = tid >> 5, lane = tid & 31;
    const int m_blk = blockIdx.y * BM;
    const int n_blk = blockIdx.x * BN;
    const int warpM = warp & 1, warpN = warp >> 1;

    // ---- load g tile into smem (pitch 20, conflict-free for generator) ----
    for (int idx = tid; idx < BM * NL; idx += 256) {
        int m = idx >> 4, l = idx & 15;
        sm[GS_OFF_F + m * GS_PITCH + l] = g_gate[(size_t)(m_blk + m) * NL + l];
    }

    // generator role: mtile = warp, fragment slot = lane
    const int q = lane >> 2, cc = lane & 3;
    const int gm0 = warp * 16 + q, gm1 = gm0 + 8;
    const float* gsr0 = sm + GS_OFF_F + gm0 * GS_PITCH;
    const float* gsr1 = sm + GS_OFF_F + gm1 * GS_PITCH;

    // B loader role
    const int f4 = tid & 7, rb = tid >> 3;

    auto loadB = [&](int c, int buf) {
        const float* src = g_pwc + (size_t)n_blk * (INF * NL) + (size_t)c * BK;
        uint32_t dst = smem_u32_of(sm + B_OFF_F + buf * B_BUF_F);
        #pragma unroll
        for (int qq = 0; qq < 8; qq++) {
            int row = rb + qq * 32;
            cp_async16(dst + (uint32_t)(row * B_PITCH + f4 * 4) * 4u,
                       src + (size_t)row * (INF * NL) + f4 * 4);
        }
        asm volatile("cp.async.commit_group;" ::: "memory");
    };
    auto loadB_bias = [&](int buf) {
        int f4b = tid & 3, rbb = tid >> 2;
        uint32_t dst = smem_u32_of(sm + B_OFF_F + buf * B_BUF_F);
        #pragma unroll
        for (int qq = 0; qq < 4; qq++) {
            int row = rbb + qq * 64;
            cp_async16(dst + (uint32_t)(row * B_PITCH + f4b * 4) * 4u,
                       pb + (size_t)(n_blk + row) * NL + f4b * 4);
        }
        asm volatile("cp.async.commit_group;" ::: "memory");
    };
    auto genA = [&](int c, int buf) {
        const float* xc0 = g_xT + (size_t)(2 * c) * BATCH + m_blk;
        const float* xc1 = xc0 + BATCH;
        float x00 = xc0[gm0], x01 = xc0[gm1];
        float x10 = xc1[gm0], x11 = xc1[gm1];
        float ga0 = gsr0[cc],     gb0 = gsr1[cc];
        float ga1 = gsr0[cc + 4], gb1 = gsr1[cc + 4];
        float ga2 = gsr0[cc + 8], gb2 = gsr1[cc + 8];
        float ga3 = gsr0[cc + 12], gb3 = gsr1[cc + 12];
        uint4* dst = (uint4*)(sm + A_OFF_F + (size_t)(buf * 8 + warp) * 4 * 128) + lane;
        dst[0]       = make_uint4(tf32r(x00*ga0), tf32r(x01*gb0), tf32r(x00*ga1), tf32r(x01*gb1));
        dst[32]      = make_uint4(tf32r(x00*ga2), tf32r(x01*gb2), tf32r(x00*ga3), tf32r(x01*gb3));
        dst[64]      = make_uint4(tf32r(x10*ga0), tf32r(x11*gb0), tf32r(x10*ga1), tf32r(x11*gb1));
        dst[96]      = make_uint4(tf32r(x10*ga2), tf32r(x11*gb2), tf32r(x10*ga3), tf32r(x11*gb3));
    };
    auto genA_bias = [&](int buf) {
        float ga0 = gsr0[cc],     gb0 = gsr1[cc];
        float ga1 = gsr0[cc + 4], gb1 = gsr1[cc + 4];
        float ga2 = gsr0[cc + 8], gb2 = gsr1[cc + 8];
        float ga3 = gsr0[cc + 12], gb3 = gsr1[cc + 12];
        uint4* dst = (uint4*)(sm + A_OFF_F + (size_t)(buf * 8 + warp) * 4 * 128) + lane;
        dst[0]  = make_uint4(tf32r(ga0), tf32r(gb0), tf32r(ga1), tf32r(gb1));
        dst[32] = make_uint4(tf32r(ga2), tf32r(gb2), tf32r(ga3), tf32r(gb3));
    };

    float acc[4][8][4];
    #pragma unroll
    for (int mt = 0; mt < 4; mt++)
        #pragma unroll
        for (int nt = 0; nt < 8; nt++)
            #pragma unroll
            for (int j = 0; j < 4; j++) acc[mt][nt][j] = 0.f;

    const float* Abase = sm + A_OFF_F;
    const float* Bbase = sm + B_OFF_F;
    const int bq = lane >> 2, bc = lane & 3;

    auto compute = [&](int buf, int nks) {
        const float* Ab = Abase + (size_t)buf * A_BUF_F + (size_t)(warpM * 4) * 4 * 128;
        const float* Bb = Bbase + (size_t)buf * B_BUF_F + (size_t)(warpN * 64 + bq) * B_PITCH;
        for (int ks = 0; ks < nks; ks++) {
            uint32_t a[4][4];
            #pragma unroll
            for (int mt = 0; mt < 4; mt++) {
                uint4 v = *(const uint4*)(Ab + (size_t)(mt * 4 + ks) * 128 + lane * 4);
                a[mt][0] = v.x; a[mt][1] = v.y; a[mt][2] = v.z; a[mt][3] = v.w;
            }
            uint32_t b[8][2];
            #pragma unroll
            for (int nt = 0; nt < 8; nt++) {
                const float* bp = Bb + nt * 8 * B_PITCH + ks * 8 + bc;
                b[nt][0] = __float_as_uint(bp[0]);
                b[nt][1] = __float_as_uint(bp[4]);
            }
            #pragma unroll
            for (int mt = 0; mt < 4; mt++)
                #pragma unroll
                for (int nt = 0; nt < 8; nt++)
                    mma_tf32(acc[mt][nt], a[mt], b[nt][0], b[nt][1]);
        }
    };

    // ---- prologue ----
    loadB(0, 0);
    __syncthreads();          // gs visible before genA
    genA(0, 0);

    // ---- main loop: one sync per iteration, 3 buffers ----
    #pragma unroll 1
    for (int it = 0; it < NTOT; it++) {
        const int nc = it + 1;
        if (nc < NIT)        { loadB(nc, nc % 3);  genA(nc, nc % 3); }
        else if (nc == NIT)  { loadB_bias(nc % 3); genA_bias(nc % 3); }
        if (nc <= NIT) asm volatile("cp.async.wait_group 1;" ::: "memory");
        else           asm volatile("cp.async.wait_group 0;" ::: "memory");
        __syncthreads();
        compute(it % 3, (it == NIT) ? 2 : 4);
    }

    // ---- epilogue: fragment store, 8B quad-coalesced ----
    #pragma unroll
    for (int mt = 0; mt < 4; mt++) {
        int m0 = m_blk + warpM * 64 + mt * 16 + (lane >> 2);
        #pragma unroll
        for (int nt = 0; nt < 8; nt++) {
            int n = n_blk + warpN * 64 + nt * 8 + 2 * (lane & 3);
            *(float2*)(out + (size_t)m0 * OUTF + n)       = make_float2(acc[mt][nt][0], acc[mt][nt][1]);
            *(float2*)(out + (size_t)(m0 + 8) * OUTF + n) = make_float2(acc[mt][nt][2], acc[mt][nt][3]);
        }
    }
}

// ---------------------------------------------------------------------------
extern "C" void kernel_launch(void* const* d_in, const int* in_sizes, int n_in,
                              void* d_out, int out_size) {
    const float* x  = (const float*)d_in[0];
    const float* gw = (const float*)d_in[1];
    const float* gb = (const float*)d_in[2];
    const float* pw = (const float*)d_in[3];
    const float* pb = (const float*)d_in[4];
    float* out = (float*)d_out;

    cudaFuncSetAttribute(gating_kernel, cudaFuncAttributeMaxDynamicSharedMemorySize,
                         INF * 17 * 4);
    cudaFuncSetAttribute(moe_mma_kernel, cudaFuncAttributeMaxDynamicSharedMemorySize,
                         SMEM_B_TOTAL);

    gating_kernel<<<BATCH / 8, 256, INF * 17 * 4>>>(x, gw, gb);
    transpose_x_kernel<<<dim3(INF / 32, BATCH / 32), dim3(32, 8)>>>(x);
    conv_pw_kernel<<<(OUTF * INF * NL) / 4 / 256, 256>>>(pw);

    dim3 grid(OUTF / BN, BATCH / BM);   // (4, 32) = 128 CTAs
    moe_mma_kernel<<<grid, 256, SMEM_B_TOTAL>>>(pb, out);
}